// round 17
// baseline (speedup 1.0000x reference)
#include <cuda_runtime.h>
#include <cuda_fp16.h>
#include <cstddef>

#define MAX_N (512 * 512)
#define NB 8

// Cell table: for each grid cell c = jj*nx+ii, 4 x uint4 (one per batch-pair p).
// Each uint4 = 4 half2: (v00,v10,v01,v11), each half2 = (batch 2p, batch 2p+1).
// 64B per cell.
__device__ uint4 g_cell[(size_t)MAX_N * 4];

// Uniform constants:
// [0]=ox(=-x0*inv_dx) [1]=oy [2]=inv_dx [3]=inv_dy [4]=nxm2 [5]=nym2 [6]=nx(bits) [7]=nxf
__device__ __align__(16) float g_consts[8];

static __device__ __forceinline__ unsigned h2u(__half2 h) {
    return *reinterpret_cast<unsigned*>(&h);
}
static __device__ __forceinline__ __half2 u2h(unsigned u) {
    return *reinterpret_cast<__half2*>(&u);
}

// ---------------------------------------------------------------------------
// Prep v9: row-paired quads. Thread = (row-pair rp, quad-col qc, batch-pair p)
// builds cell-rows 2*rp and 2*rp+1 for 4 columns, reading x rows 2rp, 2rp+1,
// 2rp+2 ONCE each: 12 loads + 15 converts + 8 stores per 8 cells
// (vs 16/20/8 in v8). NX compile-time: all row math is shift/mask.
// Thread 0 writes the interp constants inline (no serial node).
// ---------------------------------------------------------------------------
template <int NX>
__global__ void __launch_bounds__(256) prep_cell_v9(
    const float* __restrict__ x,
    const float* __restrict__ src_x,
    const float* __restrict__ src_y,
    int N)
{
    const int idx = blockIdx.x * blockDim.x + threadIdx.x;

    if (idx == 0) {
        const float x0 = src_x[0];
        const float x1 = src_x[NX - 1];
        const float y0 = src_y[0];
        const float y1 = src_y[(size_t)(NX - 1) * NX];
        const float inv_dx = (float)(NX - 1) / (x1 - x0);
        const float inv_dy = (float)(NX - 1) / (y1 - y0);
        g_consts[0] = -x0 * inv_dx;
        g_consts[1] = -y0 * inv_dy;
        g_consts[2] = inv_dx;
        g_consts[3] = inv_dy;
        g_consts[4] = (float)(NX - 2);
        g_consts[5] = (float)(NX - 2);
        g_consts[6] = __int_as_float(NX);
        g_consts[7] = (float)NX;
    }

    // NX/4 quad-columns per row-pair; NX/2 row-pairs; 4 pairs.
    constexpr int QCOLS = NX / 4;
    const int t  = idx >> 2;               // (row-pair, quad-col)
    const int p  = idx & 3;                // batch pair
    const int rp = t / QCOLS;              // row pair index
    const int qc = t - rp * QCOLS;         // quad column
    const int j0 = rp * 2;                 // first cell row of the pair
    if (j0 >= NX - 1) return;              // no cells at row NX-1
    const int ii0 = qc * 4;

    const int cA = j0 * NX + ii0;          // cell-row j0 base
    const int cB = cA + NX;                // cell-row j0+1 base (= x row j0+1)
    const int cC = cB + NX;                // x row j0+2

    const float* __restrict__ xb0 = x + (size_t)(2 * p) * N;
    const float* __restrict__ xb1 = xb0 + N;

    // Load 5-wide segments of x rows j0, j0+1, j0+2 for both planes.
    float a0[5], a1[5], a2[5];   // plane 2p
    float b0[5], b1[5], b2[5];   // plane 2p+1
    float4 v;
    v = *reinterpret_cast<const float4*>(xb0 + cA);
    a0[0] = v.x; a0[1] = v.y; a0[2] = v.z; a0[3] = v.w;
    a0[4] = __ldg(xb0 + min(cA + 4, N - 1));
    v = *reinterpret_cast<const float4*>(xb0 + cB);
    a1[0] = v.x; a1[1] = v.y; a1[2] = v.z; a1[3] = v.w;
    a1[4] = __ldg(xb0 + min(cB + 4, N - 1));
    v = *reinterpret_cast<const float4*>(xb0 + cC);
    a2[0] = v.x; a2[1] = v.y; a2[2] = v.z; a2[3] = v.w;
    a2[4] = __ldg(xb0 + min(cC + 4, N - 1));

    v = *reinterpret_cast<const float4*>(xb1 + cA);
    b0[0] = v.x; b0[1] = v.y; b0[2] = v.z; b0[3] = v.w;
    b0[4] = __ldg(xb1 + min(cA + 4, N - 1));
    v = *reinterpret_cast<const float4*>(xb1 + cB);
    b1[0] = v.x; b1[1] = v.y; b1[2] = v.z; b1[3] = v.w;
    b1[4] = __ldg(xb1 + min(cB + 4, N - 1));
    v = *reinterpret_cast<const float4*>(xb1 + cC);
    b2[0] = v.x; b2[1] = v.y; b2[2] = v.z; b2[3] = v.w;
    b2[4] = __ldg(xb1 + min(cC + 4, N - 1));

    // Convert each point exactly once.
    unsigned h0[5], h1[5], h2[5];
#pragma unroll
    for (int i = 0; i < 5; i++) {
        h0[i] = h2u(__floats2half2_rn(a0[i], b0[i]));
        h1[i] = h2u(__floats2half2_rn(a1[i], b1[i]));
        h2[i] = h2u(__floats2half2_rn(a2[i], b2[i]));
    }

    const int imax = min(4, NX - 1 - ii0);   // columns with ii <= NX-2

    // Cell-row j0: vertices from rows j0, j0+1.
    uint4* __restrict__ dstA = &g_cell[(size_t)cA * 4 + p];
#pragma unroll
    for (int i = 0; i < 4; i++) {
        if (i < imax) {
            uint4 w;
            w.x = h0[i];
            w.y = h0[i + 1];
            w.z = h1[i];
            w.w = h1[i + 1];
            dstA[(size_t)i * 4] = w;
        }
    }

    // Cell-row j0+1: vertices from rows j0+1, j0+2 (guard last row pair).
    if (j0 + 1 <= NX - 2) {
        uint4* __restrict__ dstB = &g_cell[(size_t)cB * 4 + p];
#pragma unroll
        for (int i = 0; i < 4; i++) {
            if (i < imax) {
                uint4 w;
                w.x = h1[i];
                w.y = h1[i + 1];
                w.z = h2[i];
                w.w = h2[i + 1];
                dstB[(size_t)i * 4] = w;
            }
        }
    }
}

// ---------------------------------------------------------------------------
// Interp v6 (FROZEN — converged at ~25.4us): NX compile-time, no clamps,
// branch-free weights, one LDG.128 per target per lane quad, 32 regs.
// ---------------------------------------------------------------------------
template <int NX>
__global__ void __launch_bounds__(256, 8) interp_fp16_v6(
    const float* __restrict__ tgt_x,
    const float* __restrict__ tgt_y,
    float* __restrict__ out,
    int T)
{
    const int lane = threadIdx.x & 31;
    const int warp = (blockIdx.x * blockDim.x + threadIdx.x) >> 5;
    const int g    = lane >> 2;
    const int p    = lane & 3;
    const int tg   = warp * 32 + g * 4;
    if (tg >= T) return;

    const float4 k0 = *reinterpret_cast<const float4*>(&g_consts[0]);
    const float ox = k0.x, oy = k0.y, inv_dx = k0.z, inv_dy = k0.w;

    const char* __restrict__ cellp = reinterpret_cast<const char*>(g_cell) + (p << 4);

    const bool full = (tg + 3 < T);

    float tx[4], ty[4];
    if (full) {
        const float4 tx4 = *reinterpret_cast<const float4*>(tgt_x + tg);
        const float4 ty4 = *reinterpret_cast<const float4*>(tgt_y + tg);
        tx[0] = tx4.x; tx[1] = tx4.y; tx[2] = tx4.z; tx[3] = tx4.w;
        ty[0] = ty4.x; ty[1] = ty4.y; ty[2] = ty4.z; ty[3] = ty4.w;
    } else {
#pragma unroll
        for (int j = 0; j < 4; j++) {
            const int t = min(tg + j, T - 1);
            tx[j] = tgt_x[t];
            ty[j] = tgt_y[t];
        }
    }

    float o0[4], o1[4];
#pragma unroll
    for (int j = 0; j < 4; j++) {
        const float fx = fmaf(tx[j], inv_dx, ox);
        const float fy = fmaf(ty[j], inv_dy, oy);
        const float ixf = floorf(fx);                 // in [0, NX-2] by data bounds
        const float iyf = floorf(fy);
        const float u = fx - ixf;
        const float v = fy - iyf;
        const float basef = fmaf(iyf, (float)NX, ixf);  // FFMA-imm; exact < 2^24
        const unsigned off = (unsigned)__float2int_rn(basef) << 6;

        const uint4 cv = __ldg(reinterpret_cast<const uint4*>(cellp + off));

        const float s  = u + v;
        const float m  = 1.0f - s;
        const float mn = fminf(m, 0.0f);
        const float wA  = fabsf(m);
        const float w10 = u + mn;          // lower: u      upper: 1-v
        const float w01 = v + mn;          // lower: v      upper: 1-u
        const unsigned ua = (m >= 0.0f) ? cv.x : cv.w;

        const float2 fA  = __half22float2(u2h(ua));
        const float2 f10 = __half22float2(u2h(cv.y));
        const float2 f01 = __half22float2(u2h(cv.z));

        o0[j] = fmaf(wA, fA.x, fmaf(w10, f10.x, w01 * f01.x));
        o1[j] = fmaf(wA, fA.y, fmaf(w10, f10.y, w01 * f01.y));
    }

    const int b0 = 2 * p;
    if (full) {
        *reinterpret_cast<float4*>(out + (size_t)b0 * T + tg) =
            make_float4(o0[0], o0[1], o0[2], o0[3]);
        *reinterpret_cast<float4*>(out + (size_t)(b0 + 1) * T + tg) =
            make_float4(o1[0], o1[1], o1[2], o1[3]);
    } else {
#pragma unroll
        for (int j = 0; j < 4; j++) {
            if (tg + j < T) {
                out[(size_t)b0 * T + tg + j] = o0[j];
                out[(size_t)(b0 + 1) * T + tg + j] = o1[j];
            }
        }
    }
}

// ---------------------------------------------------------------------------
// Square-grid fallback (nx != 512): consts kernel + scalar prep + runtime-nx
// interp.
// ---------------------------------------------------------------------------
__global__ void prep_consts(
    const float* __restrict__ src_x,
    const float* __restrict__ src_y,
    const int* __restrict__ p_nx,
    const int* __restrict__ p_ny)
{
    const int nx = p_nx[0];
    const int ny = p_ny[0];
    const float x0 = src_x[0];
    const float x1 = src_x[nx - 1];
    const float y0 = src_y[0];
    const float y1 = src_y[(size_t)(ny - 1) * nx];
    const float inv_dx = (float)(nx - 1) / (x1 - x0);
    const float inv_dy = (float)(ny - 1) / (y1 - y0);
    g_consts[0] = -x0 * inv_dx;
    g_consts[1] = -y0 * inv_dy;
    g_consts[2] = inv_dx;
    g_consts[3] = inv_dy;
    g_consts[4] = (float)(nx - 2);
    g_consts[5] = (float)(ny - 2);
    g_consts[6] = __int_as_float(nx);
    g_consts[7] = (float)nx;
}

__global__ void __launch_bounds__(256) prep_cell_scalar(
    const float* __restrict__ x,
    const int* __restrict__ p_nx,
    const int* __restrict__ p_ny,
    int N)
{
    const int idx = blockIdx.x * blockDim.x + threadIdx.x;
    const int c = idx >> 2;
    const int p = idx & 3;
    if (c >= N) return;
    const int nx = p_nx[0];
    const int ny = p_ny[0];
    const int jj = c / nx;
    const int ii = c - jj * nx;
    if (ii > nx - 2 || jj > ny - 2) return;

    const float* __restrict__ xb0 = x + (size_t)(2 * p) * N;
    const float* __restrict__ xb1 = xb0 + N;
    uint4 w;
    w.x = h2u(__floats2half2_rn(__ldg(xb0 + c),          __ldg(xb1 + c)));
    w.y = h2u(__floats2half2_rn(__ldg(xb0 + c + 1),      __ldg(xb1 + c + 1)));
    w.z = h2u(__floats2half2_rn(__ldg(xb0 + c + nx),     __ldg(xb1 + c + nx)));
    w.w = h2u(__floats2half2_rn(__ldg(xb0 + c + nx + 1), __ldg(xb1 + c + nx + 1)));
    g_cell[(size_t)c * 4 + p] = w;
}

__global__ void __launch_bounds__(256, 8) interp_fp16_rt(
    const float* __restrict__ tgt_x,
    const float* __restrict__ tgt_y,
    float* __restrict__ out,
    int T)
{
    const int lane = threadIdx.x & 31;
    const int warp = (blockIdx.x * blockDim.x + threadIdx.x) >> 5;
    const int g    = lane >> 2;
    const int p    = lane & 3;
    const int tg   = warp * 32 + g * 4;
    if (tg >= T) return;

    const float4 k0 = *reinterpret_cast<const float4*>(&g_consts[0]);
    const float4 k1 = *reinterpret_cast<const float4*>(&g_consts[4]);
    const float ox = k0.x, oy = k0.y, inv_dx = k0.z, inv_dy = k0.w;
    const float nxf = k1.w;

    const char* __restrict__ cellp = reinterpret_cast<const char*>(g_cell) + (p << 4);
    const bool full = (tg + 3 < T);

    float tx[4], ty[4];
    if (full) {
        const float4 tx4 = *reinterpret_cast<const float4*>(tgt_x + tg);
        const float4 ty4 = *reinterpret_cast<const float4*>(tgt_y + tg);
        tx[0] = tx4.x; tx[1] = tx4.y; tx[2] = tx4.z; tx[3] = tx4.w;
        ty[0] = ty4.x; ty[1] = ty4.y; ty[2] = ty4.z; ty[3] = ty4.w;
    } else {
#pragma unroll
        for (int j = 0; j < 4; j++) {
            const int t = min(tg + j, T - 1);
            tx[j] = tgt_x[t];
            ty[j] = tgt_y[t];
        }
    }

    float o0[4], o1[4];
#pragma unroll
    for (int j = 0; j < 4; j++) {
        const float fx = fmaf(tx[j], inv_dx, ox);
        const float fy = fmaf(ty[j], inv_dy, oy);
        const float ixf = floorf(fx);
        const float iyf = floorf(fy);
        const float u = fx - ixf;
        const float v = fy - iyf;
        const float basef = fmaf(iyf, nxf, ixf);
        const unsigned off = (unsigned)__float2int_rn(basef) << 6;

        const uint4 cv = __ldg(reinterpret_cast<const uint4*>(cellp + off));

        const float s  = u + v;
        const float m  = 1.0f - s;
        const float mn = fminf(m, 0.0f);
        const float wA  = fabsf(m);
        const float w10 = u + mn;
        const float w01 = v + mn;
        const unsigned ua = (m >= 0.0f) ? cv.x : cv.w;

        const float2 fA  = __half22float2(u2h(ua));
        const float2 f10 = __half22float2(u2h(cv.y));
        const float2 f01 = __half22float2(u2h(cv.z));

        o0[j] = fmaf(wA, fA.x, fmaf(w10, f10.x, w01 * f01.x));
        o1[j] = fmaf(wA, fA.y, fmaf(w10, f10.y, w01 * f01.y));
    }

    const int b0 = 2 * p;
    if (full) {
        *reinterpret_cast<float4*>(out + (size_t)b0 * T + tg) =
            make_float4(o0[0], o0[1], o0[2], o0[3]);
        *reinterpret_cast<float4*>(out + (size_t)(b0 + 1) * T + tg) =
            make_float4(o1[0], o1[1], o1[2], o1[3]);
    } else {
#pragma unroll
        for (int j = 0; j < 4; j++) {
            if (tg + j < T) {
                out[(size_t)b0 * T + tg + j] = o0[j];
                out[(size_t)(b0 + 1) * T + tg + j] = o1[j];
            }
        }
    }
}

// ---------------------------------------------------------------------------
// Generic fallback (any B), fp32 exact, full clamping.
// ---------------------------------------------------------------------------
__global__ void interp_generic_kernel(
    const float* __restrict__ x,
    const float* __restrict__ src_x,
    const float* __restrict__ src_y,
    const float* __restrict__ tgt_x,
    const float* __restrict__ tgt_y,
    const int* __restrict__ p_nx,
    const int* __restrict__ p_ny,
    float* __restrict__ out,
    int T, int B, int N)
{
    int t = blockIdx.x * blockDim.x + threadIdx.x;
    if (t >= T) return;

    const int nx = p_nx[0];
    const int ny = p_ny[0];
    const float x0 = src_x[0];
    const float x1 = src_x[nx - 1];
    const float y0 = src_y[0];
    const float y1 = src_y[(size_t)(ny - 1) * nx];
    const float inv_dx = (float)(nx - 1) / (x1 - x0);
    const float inv_dy = (float)(ny - 1) / (y1 - y0);

    const float fx = (tgt_x[t] - x0) * inv_dx;
    const float fy = (tgt_y[t] - y0) * inv_dy;

    float ixf = fminf(fmaxf(floorf(fx), 0.0f), (float)(nx - 2));
    float iyf = fminf(fmaxf(floorf(fy), 0.0f), (float)(ny - 2));
    const float u = fx - ixf;
    const float v = fy - iyf;
    const int base = (int)iyf * nx + (int)ixf;

    const bool lower = (u + v <= 1.0f);
    const int iA = lower ? base : (base + nx + 1);
    const int iB = base + 1;
    const int iC = base + nx;
    const float wA = lower ? (1.0f - u - v) : (u + v - 1.0f);
    const float wB = lower ? u : (1.0f - v);
    const float wC = lower ? v : (1.0f - u);

    for (int b = 0; b < B; b++) {
        const float* xb = x + (size_t)b * N;
        out[(size_t)b * T + t] = wA * xb[iA] + wB * xb[iB] + wC * xb[iC];
    }
}

extern "C" void kernel_launch(void* const* d_in, const int* in_sizes, int n_in,
                              void* d_out, int out_size)
{
    const float* x     = (const float*)d_in[0];
    const float* src_x = (const float*)d_in[1];
    const float* src_y = (const float*)d_in[2];
    const float* tgt_x = (const float*)d_in[3];
    const float* tgt_y = (const float*)d_in[4];
    const int*   p_nx  = (const int*)d_in[5];
    const int*   p_ny  = (const int*)d_in[6];
    float* out = (float*)d_out;

    const int N = in_sizes[1];          // nx*ny grid points
    const int T = in_sizes[3];          // target count
    const int B = in_sizes[0] / N;      // batches

    if (B == NB && N <= MAX_N) {
        // Host-side shape inference: square grid.
        int nxh = 1;
        while (nxh * nxh < N) nxh++;
        const bool square = (nxh * nxh == N);
        const int blocks = (T + 255) / 256;

        if (square && nxh == 512) {
            // Fast path: NX=512, 2 kernel nodes, row-paired prep.
            // threads = (rows/2) * (cols/4) * 4 pairs = N/2.
            const int prep_threads = N / 2;
            prep_cell_v9<512><<<(prep_threads + 255) / 256, 256>>>(
                x, src_x, src_y, N);
            interp_fp16_v6<512><<<blocks, 256>>>(tgt_x, tgt_y, out, T);
        } else {
            prep_consts<<<1, 1>>>(src_x, src_y, p_nx, p_ny);
            const int prep_threads = 4 * N;
            prep_cell_scalar<<<(prep_threads + 255) / 256, 256>>>(x, p_nx, p_ny, N);
            interp_fp16_rt<<<blocks, 256>>>(tgt_x, tgt_y, out, T);
        }
    } else {
        const int threads = 256;
        interp_generic_kernel<<<(T + threads - 1) / threads, threads>>>(
            x, src_x, src_y, tgt_x, tgt_y, p_nx, p_ny, out, T, B, N);
    }
}